// round 12
// baseline (speedup 1.0000x reference)
#include <cuda_runtime.h>

// EdgeUpdateNetwork: T=8, N=256, F=128
//
// Factorization: y[t,i,j,f] = A[t,i,f] + B[t,j,f] where
//   A = x @ w[:, :F]^T,  B = x @ w[:, F:]^T
// BN stats in closed form from A/B reductions; then fused
// affine+relu+diag-zero+L1-normalize streaming kernel writes 537MB.

#define T_DIM 8
#define N_DIM 256
#define F_DIM 128
#define M_DIM (T_DIM * N_DIM)   // 2048 rows
#define O_DIM 512               // A1 | B1 | A2 | B2

// Scratch (device globals — no allocation allowed)
__device__ float g_Y[M_DIM * O_DIM];   // 4 MB: Y[m][o]
__device__ float g_sh[4 * F_DIM];      // [br*256 + f] = scale, [br*256+128+f] = shift

// ---------------------------------------------------------------------------
// Kernel 1: X[2048,128] @ W^T[128,512] -> Y[2048,512]
// 64x64 tile, 256 threads (8 warps), 4x4 micro-tile, grid (8,32)=256 blocks.
// Double-buffered smem: ONE __syncthreads per K-chunk. (Proven R8 version.)
// ---------------------------------------------------------------------------
__global__ void __launch_bounds__(256) gemm_kernel(const float* __restrict__ X,
                                                   const float* __restrict__ w1,
                                                   const float* __restrict__ w2) {
    __shared__ float Xs[2][16][68];   // [buf][kk][m]
    __shared__ float Ws[2][16][68];   // [buf][kk][o]

    const int m0 = blockIdx.y * 64;
    const int o0 = blockIdx.x * 64;
    const int tid = threadIdx.x;
    const int tx = tid & 15;          // o: cols tx*4 .. tx*4+3
    const int ty = tid >> 4;          // m: rows ty*4 .. ty*4+3 (ty 0..15)
    const float* wbase = (o0 < 256) ? w1 : w2;   // o0 mult of 64, never straddles

    // Per-chunk loads: X tile 64x16 = 256 float4, 1 per thread; W likewise.
    const int xr = tid >> 2, xq = tid & 3;                 // row 0..63, quad 0..3
    const float* xp = X + (m0 + xr) * 128 + xq * 4;
    const float* wp = wbase + ((o0 + xr) & 127) * 256 + (((o0 + xr) >> 7) & 1) * 128 + xq * 4;

    float acc[4][4] = {};
    float4 px, pw;

    // prefetch chunk 0 and stage into buffer 0
    px = *(const float4*)&xp[0];
    pw = *(const float4*)&wp[0];
    Xs[0][xq * 4 + 0][xr] = px.x;  Xs[0][xq * 4 + 1][xr] = px.y;
    Xs[0][xq * 4 + 2][xr] = px.z;  Xs[0][xq * 4 + 3][xr] = px.w;
    Ws[0][xq * 4 + 0][xr] = pw.x;  Ws[0][xq * 4 + 1][xr] = pw.y;
    Ws[0][xq * 4 + 2][xr] = pw.z;  Ws[0][xq * 4 + 3][xr] = pw.w;
    __syncthreads();

    #pragma unroll
    for (int c = 0; c < 8; c++) {
        const int cur = c & 1, nxt = cur ^ 1;
        if (c < 7) {
            const int kc = (c + 1) * 16;
            px = *(const float4*)&xp[kc];
            pw = *(const float4*)&wp[kc];
        }

        #pragma unroll
        for (int kk = 0; kk < 16; kk++) {
            const float4 xa = *(const float4*)&Xs[cur][kk][ty * 4];
            const float4 wr = *(const float4*)&Ws[cur][kk][tx * 4];
            const float xv[4] = {xa.x, xa.y, xa.z, xa.w};
            const float wv[4] = {wr.x, wr.y, wr.z, wr.w};
            #pragma unroll
            for (int a = 0; a < 4; a++)
                #pragma unroll
                for (int b = 0; b < 4; b++)
                    acc[a][b] = fmaf(xv[a], wv[b], acc[a][b]);
        }

        if (c < 7) {
            // Writing the OTHER buffer: safe while peers read `cur`.
            Xs[nxt][xq * 4 + 0][xr] = px.x;  Xs[nxt][xq * 4 + 1][xr] = px.y;
            Xs[nxt][xq * 4 + 2][xr] = px.z;  Xs[nxt][xq * 4 + 3][xr] = px.w;
            Ws[nxt][xq * 4 + 0][xr] = pw.x;  Ws[nxt][xq * 4 + 1][xr] = pw.y;
            Ws[nxt][xq * 4 + 2][xr] = pw.z;  Ws[nxt][xq * 4 + 3][xr] = pw.w;
            __syncthreads();
        }
    }

    #pragma unroll
    for (int a = 0; a < 4; a++) {
        float4 v = make_float4(acc[a][0], acc[a][1], acc[a][2], acc[a][3]);
        *(float4*)&g_Y[(m0 + ty * 4 + a) * O_DIM + o0 + tx * 4] = v;
    }
}

// ---------------------------------------------------------------------------
// Kernel 2: closed-form BN stats, COALESCED.
// 32 blocks: (br, fg) -> 8 f's of one branch. Block reads both the A strip
// (cols colA..colA+7) and B strip (colA+128..+135) of g_Y with float4
// row-major loads (full sector utilization, 4 MB total vs 32 MB of sectors
// in the strided version). Per-t sums for the cross term via shfl + smem;
// then fold s = g*rstd, h = b - mean*s.
// ---------------------------------------------------------------------------
__global__ void __launch_bounds__(256) stats_kernel(const float* __restrict__ gamma1,
                                                    const float* __restrict__ beta1,
                                                    const float* __restrict__ gamma2,
                                                    const float* __restrict__ beta2) {
    const int bid = blockIdx.x;          // 32 blocks
    const int br = bid >> 4, fg = bid & 15;
    const int fb = fg * 8;
    const int colA = br * 256 + fb;
    const int tid = threadIdx.x;
    const int w = tid >> 5, l = tid & 31;
    const int r = tid >> 2;              // 0..63 row-slot
    const int slot = tid & 3;            // 0,1 -> A(+0,+4); 2,3 -> B(+0,+4)
    const int coff = colA + (slot >> 1) * 128 + (slot & 1) * 4;

    __shared__ float4 SWT[8][4];         // per-warp per-slot partials
    __shared__ float  SMT[8][16];        // per-t col sums: [t][0..7]=A f, [8..15]=B f
    __shared__ float  SQf[16];           // col sum-of-squares

    float4 sq = make_float4(0.f, 0.f, 0.f, 0.f);

    #pragma unroll 1
    for (int t = 0; t < 8; t++) {
        float4 st = make_float4(0.f, 0.f, 0.f, 0.f);
        #pragma unroll
        for (int k = 0; k < 4; k++) {
            const int m = t * 256 + k * 64 + r;
            const float4 v = *(const float4*)&g_Y[m * O_DIM + coff];
            st.x += v.x;  st.y += v.y;  st.z += v.z;  st.w += v.w;
            sq.x = fmaf(v.x, v.x, sq.x);  sq.y = fmaf(v.y, v.y, sq.y);
            sq.z = fmaf(v.z, v.z, sq.z);  sq.w = fmaf(v.w, v.w, sq.w);
        }
        // reduce over the 8 same-slot lanes (stride 4) in this warp
        #pragma unroll
        for (int off = 4; off < 32; off <<= 1) {
            st.x += __shfl_xor_sync(0xffffffffu, st.x, off);
            st.y += __shfl_xor_sync(0xffffffffu, st.y, off);
            st.z += __shfl_xor_sync(0xffffffffu, st.z, off);
            st.w += __shfl_xor_sync(0xffffffffu, st.w, off);
        }
        if (l < 4) SWT[w][l] = st;       // lane l holds slot l
        __syncthreads();
        if (w == 0) {
            float4 v = SWT[l >> 2][l & 3];
            #pragma unroll
            for (int off = 4; off < 32; off <<= 1) {
                v.x += __shfl_xor_sync(0xffffffffu, v.x, off);
                v.y += __shfl_xor_sync(0xffffffffu, v.y, off);
                v.z += __shfl_xor_sync(0xffffffffu, v.z, off);
                v.w += __shfl_xor_sync(0xffffffffu, v.w, off);
            }
            if (l < 4) {                 // slot l -> cols l*4..+3 of [A0..7,B0..7]
                SMT[t][l * 4 + 0] = v.x;  SMT[t][l * 4 + 1] = v.y;
                SMT[t][l * 4 + 2] = v.z;  SMT[t][l * 4 + 3] = v.w;
            }
        }
        __syncthreads();
    }

    // reduce sum-of-squares the same way (once)
    #pragma unroll
    for (int off = 4; off < 32; off <<= 1) {
        sq.x += __shfl_xor_sync(0xffffffffu, sq.x, off);
        sq.y += __shfl_xor_sync(0xffffffffu, sq.y, off);
        sq.z += __shfl_xor_sync(0xffffffffu, sq.z, off);
        sq.w += __shfl_xor_sync(0xffffffffu, sq.w, off);
    }
    if (l < 4) SWT[w][l] = sq;
    __syncthreads();
    if (w == 0) {
        float4 v = SWT[l >> 2][l & 3];
        #pragma unroll
        for (int off = 4; off < 32; off <<= 1) {
            v.x += __shfl_xor_sync(0xffffffffu, v.x, off);
            v.y += __shfl_xor_sync(0xffffffffu, v.y, off);
            v.z += __shfl_xor_sync(0xffffffffu, v.z, off);
            v.w += __shfl_xor_sync(0xffffffffu, v.w, off);
        }
        if (l < 4) {
            SQf[l * 4 + 0] = v.x;  SQf[l * 4 + 1] = v.y;
            SQf[l * 4 + 2] = v.z;  SQf[l * 4 + 3] = v.w;
        }
    }
    __syncthreads();

    if (tid < 8) {
        const int f = tid;
        float sumA = 0.f, sumB = 0.f, cross = 0.f;
        #pragma unroll
        for (int t = 0; t < 8; t++) {
            const float a = SMT[t][f], b = SMT[t][8 + f];
            sumA += a;  sumB += b;  cross = fmaf(a, b, cross);
        }
        const float sqA = SQf[f], sqB = SQf[8 + f];
        const float mean = (sumA + sumB) * (1.0f / 2048.0f);
        const float ey2  = (256.0f * (sqA + sqB) + 2.0f * cross) * (1.0f / 524288.0f);
        const float var  = ey2 - mean * mean;
        const int fglob = fb + f;
        const float g  = br ? gamma2[fglob] : gamma1[fglob];
        const float bb = br ? beta2[fglob]  : beta1[fglob];
        const float s  = g * rsqrtf(var + 1e-5f);
        g_sh[br * 256 + fglob]       = s;
        g_sh[br * 256 + 128 + fglob] = bb - mean * s;
    }
}

// ---------------------------------------------------------------------------
// Kernel 3: streaming epilogue (write-bound, 537 MB).
// 2048 blocks x 128 threads: block = (t, br, 8-row i-tile, j-quarter);
// 2048/148 = 13.8 blocks/SM -> ~1% wave tail. Warp w handles 16 j's;
// j OUTER, i inner: each b4 load reused for 8 i-rows, p[ii]=fma(a,s,h)
// in registers. Streaming stores (__stcs).
// ---------------------------------------------------------------------------
__global__ void __launch_bounds__(128) edge_kernel(float* __restrict__ out) {
    const int bid = blockIdx.x;          // 2048 blocks
    const int jq = bid & 3;
    const int itile = (bid >> 2) & 31;
    const int br = (bid >> 7) & 1;
    const int t = bid >> 8;
    const int i0 = itile * 8;
    const int tid = threadIdx.x;
    const int w = tid >> 5, l = tid & 31;
    const int f0 = l * 4;
    const int j0 = jq * 64 + w * 16;

    const float4 s4 = *(const float4*)&g_sh[br * 256 + f0];
    const float4 h4 = *(const float4*)&g_sh[br * 256 + 128 + f0];
    const int baseA = br * 256 + f0;
    const int baseB = baseA + 128;

    float4 p[8];
    #pragma unroll
    for (int ii = 0; ii < 8; ii++) {
        const float4 a4 = *(const float4*)&g_Y[(t * 256 + i0 + ii) * O_DIM + baseA];
        p[ii].x = fmaf(a4.x, s4.x, h4.x);
        p[ii].y = fmaf(a4.y, s4.y, h4.y);
        p[ii].z = fmaf(a4.z, s4.z, h4.z);
        p[ii].w = fmaf(a4.w, s4.w, h4.w);
    }

    // out index: (((t*2+br)*256 + i) * 256 + j) * 128 + f
    const size_t outbase = (size_t)((t * 2 + br) * 256 + i0) * (256 * 128);

    #pragma unroll 2
    for (int jj = 0; jj < 16; jj++) {
        const int j = j0 + jj;
        const float4 b4 = *(const float4*)&g_Y[(t * 256 + j) * O_DIM + baseB];
        float* orow = out + outbase + (size_t)j * 128 + f0;
        #pragma unroll
        for (int ii = 0; ii < 8; ii++) {
            float vx = fmaxf(fmaf(b4.x, s4.x, p[ii].x), 0.0f);
            float vy = fmaxf(fmaf(b4.y, s4.y, p[ii].y), 0.0f);
            float vz = fmaxf(fmaf(b4.z, s4.z, p[ii].z), 0.0f);
            float vw = fmaxf(fmaf(b4.w, s4.w, p[ii].w), 0.0f);
            if (j == i0 + ii) { vx = 0.f; vy = 0.f; vz = 0.f; vw = 0.f; }
            float sm = (vx + vy) + (vz + vw);
            #pragma unroll
            for (int off = 16; off; off >>= 1)
                sm += __shfl_xor_sync(0xffffffffu, sm, off);
            const float inv = __fdividef(1.0f, fmaxf(sm, 1e-12f));
            float4 o4 = make_float4(vx * inv, vy * inv, vz * inv, vw * inv);
            __stcs((float4*)(orow + (size_t)ii * (256 * 128)), o4);
        }
    }
}

// ---------------------------------------------------------------------------
extern "C" void kernel_launch(void* const* d_in, const int* in_sizes, int n_in,
                              void* d_out, int out_size) {
    const float* x  = (const float*)d_in[0];   // node_feats [8,256,128]
    const float* w1 = (const float*)d_in[1];   // [128,256]
    const float* g1 = (const float*)d_in[2];
    const float* b1 = (const float*)d_in[3];
    const float* w2 = (const float*)d_in[4];
    const float* g2 = (const float*)d_in[5];
    const float* b2 = (const float*)d_in[6];
    float* out = (float*)d_out;                // [8,2,256,256,128] fp32

    dim3 ggrid(O_DIM / 64, M_DIM / 64);        // (8, 32) = 256 blocks
    gemm_kernel<<<ggrid, 256>>>(x, w1, w2);
    stats_kernel<<<32, 256>>>(g1, b1, g2, b2);
    edge_kernel<<<2048, 128>>>(out);
}

// round 13
// speedup vs baseline: 1.0534x; 1.0534x over previous
#include <cuda_runtime.h>

// EdgeUpdateNetwork: T=8, N=256, F=128
//
// Factorization: y[t,i,j,f] = A[t,i,f] + B[t,j,f] where
//   A = x @ w[:, :F]^T,  B = x @ w[:, F:]^T
// BN stats in closed form from A/B reductions; then fused
// affine+relu+diag-zero+L1-normalize streaming kernel writes 537MB.

#define T_DIM 8
#define N_DIM 256
#define F_DIM 128
#define M_DIM (T_DIM * N_DIM)   // 2048 rows
#define O_DIM 512               // A1 | B1 | A2 | B2

// Scratch (device globals — no allocation allowed)
__device__ float g_Y[M_DIM * O_DIM];   // 4 MB: Y[m][o]
__device__ float g_sh[4 * F_DIM];      // [br*256 + f] = scale, [br*256+128+f] = shift

// ---------------------------------------------------------------------------
// Kernel 1: X[2048,128] @ W^T[128,512] -> Y[2048,512]
// 64x64 tile, 256 threads, 4x4 micro-tile, grid (8,32)=256 blocks.
// SINGLE K-chunk: whole X tile (float4 [kq][m]) + whole W tile ([kk][o])
// staged once -> exactly ONE __syncthreads, all 16 LDG.128 front-batched.
// (R10 design; the k-offset bug xp[16*r*4] -> xp[16*r] is fixed.)
// ---------------------------------------------------------------------------
__global__ void __launch_bounds__(256) gemm_kernel(const float* __restrict__ X,
                                                   const float* __restrict__ w1,
                                                   const float* __restrict__ w2) {
    __shared__ float4 Xs4[32][65];    // [kq][m]: X[m0+m][kq*4 .. kq*4+3]
    __shared__ float  Ws[128][68];    // [kk][o]

    const int m0 = blockIdx.y * 64;
    const int o0 = blockIdx.x * 64;
    const int tid = threadIdx.x;
    const int tx = tid & 15;          // o: cols tx*4 .. tx*4+3
    const int ty = tid >> 4;          // m: rows ty*4 .. ty*4+3
    const float* wbase = (o0 < 256) ? w1 : w2;   // o0 mult of 64, never straddles

    const int d = tid >> 2;           // 0..63 (row for X, o for W)
    const int kq0 = tid & 3;
    const float* xp = X + (m0 + d) * 128 + kq0 * 4;
    const int wf = (o0 + d) & 127, wh = ((o0 + d) >> 7) & 1;
    const float* wp = wbase + wf * 256 + wh * 128 + kq0 * 4;

    // Stage whole tiles: 8 float4 of X + 8 float4 of W per thread.
    // k for step r is kq*4 = kq0*4 + 16*r -> offset from xp/wp is 16*r floats.
    #pragma unroll
    for (int r = 0; r < 8; r++) {
        const int kq = kq0 + 4 * r;
        const float4 px = *(const float4*)&xp[16 * r];
        const float4 pw = *(const float4*)&wp[16 * r];
        Xs4[kq][d] = px;                                        // STS.128
        Ws[kq * 4 + 0][d] = pw.x;  Ws[kq * 4 + 1][d] = pw.y;   // transpose
        Ws[kq * 4 + 2][d] = pw.z;  Ws[kq * 4 + 3][d] = pw.w;
    }
    __syncthreads();

    float acc[4][4] = {};

    #pragma unroll 4
    for (int kq = 0; kq < 32; kq++) {
        float4 xv[4], wr[4];
        #pragma unroll
        for (int a = 0; a < 4; a++) xv[a] = Xs4[kq][ty * 4 + a];          // broadcast
        #pragma unroll
        for (int c = 0; c < 4; c++) wr[c] = *(const float4*)&Ws[kq * 4 + c][tx * 4];
        #pragma unroll
        for (int a = 0; a < 4; a++) {
            acc[a][0] = fmaf(xv[a].x, wr[0].x, acc[a][0]);
            acc[a][1] = fmaf(xv[a].x, wr[0].y, acc[a][1]);
            acc[a][2] = fmaf(xv[a].x, wr[0].z, acc[a][2]);
            acc[a][3] = fmaf(xv[a].x, wr[0].w, acc[a][3]);
            acc[a][0] = fmaf(xv[a].y, wr[1].x, acc[a][0]);
            acc[a][1] = fmaf(xv[a].y, wr[1].y, acc[a][1]);
            acc[a][2] = fmaf(xv[a].y, wr[1].z, acc[a][2]);
            acc[a][3] = fmaf(xv[a].y, wr[1].w, acc[a][3]);
            acc[a][0] = fmaf(xv[a].z, wr[2].x, acc[a][0]);
            acc[a][1] = fmaf(xv[a].z, wr[2].y, acc[a][1]);
            acc[a][2] = fmaf(xv[a].z, wr[2].z, acc[a][2]);
            acc[a][3] = fmaf(xv[a].z, wr[2].w, acc[a][3]);
            acc[a][0] = fmaf(xv[a].w, wr[3].x, acc[a][0]);
            acc[a][1] = fmaf(xv[a].w, wr[3].y, acc[a][1]);
            acc[a][2] = fmaf(xv[a].w, wr[3].z, acc[a][2]);
            acc[a][3] = fmaf(xv[a].w, wr[3].w, acc[a][3]);
        }
    }

    #pragma unroll
    for (int a = 0; a < 4; a++) {
        float4 v = make_float4(acc[a][0], acc[a][1], acc[a][2], acc[a][3]);
        *(float4*)&g_Y[(m0 + ty * 4 + a) * O_DIM + o0 + tx * 4] = v;
    }
}

// ---------------------------------------------------------------------------
// Kernel 2: closed-form BN stats. 32 blocks (br, fg) x 512 threads.
// Each 64-thread group owns one t: r0 = 0..15 rows x4, slot = which 4 cols
// (A+0, A+4, B+0, B+4 of the 8-f strip). float4 loads: adjacent lane pairs
// fill 32B sectors. Warp shfl reduce -> per-t sums in smem -> fold
// s = g*rstd, h = b - mean*s. Only 3 __syncthreads (was 16 in R12).
// ---------------------------------------------------------------------------
__global__ void __launch_bounds__(512) stats_kernel(const float* __restrict__ gamma1,
                                                    const float* __restrict__ beta1,
                                                    const float* __restrict__ gamma2,
                                                    const float* __restrict__ beta2) {
    const int bid = blockIdx.x;          // 32 blocks
    const int br = bid >> 4, fg = bid & 15;
    const int fb = fg * 8;
    const int colA = br * 256 + fb;
    const int tid = threadIdx.x;
    const int w = tid >> 5, l = tid & 31;
    const int tw = tid >> 6;             // t this 64-thread group owns
    const int t64 = tid & 63;
    const int r0 = t64 >> 2;             // 0..15
    const int slot = t64 & 3;            // 0:A+0 1:A+4 2:B+0 3:B+4
    const int coff = colA + (slot >> 1) * 128 + (slot & 1) * 4;

    __shared__ float SW[16][16];         // [warp][slot*4+comp] sum partials
    __shared__ float SQ[16][16];         // sum-of-squares partials
    __shared__ float TA[8][8], TB[8][8], QA[8][8], QB[8][8];

    float4 st = make_float4(0.f, 0.f, 0.f, 0.f);
    float4 sq = make_float4(0.f, 0.f, 0.f, 0.f);
    #pragma unroll
    for (int k = 0; k < 16; k++) {
        const int m = tw * 256 + k * 16 + r0;
        const float4 v = *(const float4*)&g_Y[m * O_DIM + coff];
        st.x += v.x;  st.y += v.y;  st.z += v.z;  st.w += v.w;
        sq.x = fmaf(v.x, v.x, sq.x);  sq.y = fmaf(v.y, v.y, sq.y);
        sq.z = fmaf(v.z, v.z, sq.z);  sq.w = fmaf(v.w, v.w, sq.w);
    }
    // reduce over r0 within warp (same-slot lanes are stride 4)
    #pragma unroll
    for (int off = 4; off < 32; off <<= 1) {
        st.x += __shfl_xor_sync(0xffffffffu, st.x, off);
        st.y += __shfl_xor_sync(0xffffffffu, st.y, off);
        st.z += __shfl_xor_sync(0xffffffffu, st.z, off);
        st.w += __shfl_xor_sync(0xffffffffu, st.w, off);
        sq.x += __shfl_xor_sync(0xffffffffu, sq.x, off);
        sq.y += __shfl_xor_sync(0xffffffffu, sq.y, off);
        sq.z += __shfl_xor_sync(0xffffffffu, sq.z, off);
        sq.w += __shfl_xor_sync(0xffffffffu, sq.w, off);
    }
    if (l < 4) {                          // lane l holds slot l
        SW[w][l * 4 + 0] = st.x;  SW[w][l * 4 + 1] = st.y;
        SW[w][l * 4 + 2] = st.z;  SW[w][l * 4 + 3] = st.w;
        SQ[w][l * 4 + 0] = sq.x;  SQ[w][l * 4 + 1] = sq.y;
        SQ[w][l * 4 + 2] = sq.z;  SQ[w][l * 4 + 3] = sq.w;
    }
    __syncthreads();

    // combine the two warps of each t-group (t uses warps 2t, 2t+1)
    if (tid < 64) {
        const int t = tid >> 3, fi = tid & 7;
        const int sl = fi >> 2, cp = fi & 3;
        TA[t][fi] = SW[2 * t][sl * 4 + cp]       + SW[2 * t + 1][sl * 4 + cp];
        TB[t][fi] = SW[2 * t][(2 + sl) * 4 + cp] + SW[2 * t + 1][(2 + sl) * 4 + cp];
        QA[t][fi] = SQ[2 * t][sl * 4 + cp]       + SQ[2 * t + 1][sl * 4 + cp];
        QB[t][fi] = SQ[2 * t][(2 + sl) * 4 + cp] + SQ[2 * t + 1][(2 + sl) * 4 + cp];
    }
    __syncthreads();

    if (tid < 8) {
        const int fi = tid;
        float sumA = 0.f, sumB = 0.f, cross = 0.f, sqA = 0.f, sqB = 0.f;
        #pragma unroll
        for (int t = 0; t < 8; t++) {
            const float a = TA[t][fi], b = TB[t][fi];
            sumA += a;  sumB += b;  cross = fmaf(a, b, cross);
            sqA += QA[t][fi];  sqB += QB[t][fi];
        }
        const float mean = (sumA + sumB) * (1.0f / 2048.0f);
        const float ey2  = (256.0f * (sqA + sqB) + 2.0f * cross) * (1.0f / 524288.0f);
        const float var  = ey2 - mean * mean;
        const int fglob = fb + fi;
        const float g  = br ? gamma2[fglob] : gamma1[fglob];
        const float bb = br ? beta2[fglob]  : beta1[fglob];
        const float s  = g * rsqrtf(var + 1e-5f);
        g_sh[br * 256 + fglob]       = s;
        g_sh[br * 256 + 128 + fglob] = bb - mean * s;
    }
}

// ---------------------------------------------------------------------------
// Kernel 3: streaming epilogue (write-bound, 537 MB).
// 2048 blocks x 128 threads: block = (t, br, 8-row i-tile, j-quarter);
// 2048/148 = 13.8 blocks/SM -> ~1% wave tail. Warp w handles 16 j's;
// j OUTER, i inner: each b4 load reused for 8 i-rows, p[ii]=fma(a,s,h)
// in registers. Streaming stores (__stcs).
// ---------------------------------------------------------------------------
__global__ void __launch_bounds__(128) edge_kernel(float* __restrict__ out) {
    const int bid = blockIdx.x;          // 2048 blocks
    const int jq = bid & 3;
    const int itile = (bid >> 2) & 31;
    const int br = (bid >> 7) & 1;
    const int t = bid >> 8;
    const int i0 = itile * 8;
    const int tid = threadIdx.x;
    const int w = tid >> 5, l = tid & 31;
    const int f0 = l * 4;
    const int j0 = jq * 64 + w * 16;

    const float4 s4 = *(const float4*)&g_sh[br * 256 + f0];
    const float4 h4 = *(const float4*)&g_sh[br * 256 + 128 + f0];
    const int baseA = br * 256 + f0;
    const int baseB = baseA + 128;

    float4 p[8];
    #pragma unroll
    for (int ii = 0; ii < 8; ii++) {
        const float4 a4 = *(const float4*)&g_Y[(t * 256 + i0 + ii) * O_DIM + baseA];
        p[ii].x = fmaf(a4.x, s4.x, h4.x);
        p[ii].y = fmaf(a4.y, s4.y, h4.y);
        p[ii].z = fmaf(a4.z, s4.z, h4.z);
        p[ii].w = fmaf(a4.w, s4.w, h4.w);
    }

    // out index: (((t*2+br)*256 + i) * 256 + j) * 128 + f
    const size_t outbase = (size_t)((t * 2 + br) * 256 + i0) * (256 * 128);

    #pragma unroll 2
    for (int jj = 0; jj < 16; jj++) {
        const int j = j0 + jj;
        const float4 b4 = *(const float4*)&g_Y[(t * 256 + j) * O_DIM + baseB];
        float* orow = out + outbase + (size_t)j * 128 + f0;
        #pragma unroll
        for (int ii = 0; ii < 8; ii++) {
            float vx = fmaxf(fmaf(b4.x, s4.x, p[ii].x), 0.0f);
            float vy = fmaxf(fmaf(b4.y, s4.y, p[ii].y), 0.0f);
            float vz = fmaxf(fmaf(b4.z, s4.z, p[ii].z), 0.0f);
            float vw = fmaxf(fmaf(b4.w, s4.w, p[ii].w), 0.0f);
            if (j == i0 + ii) { vx = 0.f; vy = 0.f; vz = 0.f; vw = 0.f; }
            float sm = (vx + vy) + (vz + vw);
            #pragma unroll
            for (int off = 16; off; off >>= 1)
                sm += __shfl_xor_sync(0xffffffffu, sm, off);
            const float inv = __fdividef(1.0f, fmaxf(sm, 1e-12f));
            float4 o4 = make_float4(vx * inv, vy * inv, vz * inv, vw * inv);
            __stcs((float4*)(orow + (size_t)ii * (256 * 128)), o4);
        }
    }
}

// ---------------------------------------------------------------------------
extern "C" void kernel_launch(void* const* d_in, const int* in_sizes, int n_in,
                              void* d_out, int out_size) {
    const float* x  = (const float*)d_in[0];   // node_feats [8,256,128]
    const float* w1 = (const float*)d_in[1];   // [128,256]
    const float* g1 = (const float*)d_in[2];
    const float* b1 = (const float*)d_in[3];
    const float* w2 = (const float*)d_in[4];
    const float* g2 = (const float*)d_in[5];
    const float* b2 = (const float*)d_in[6];
    float* out = (float*)d_out;                // [8,2,256,256,128] fp32

    dim3 ggrid(O_DIM / 64, M_DIM / 64);        // (8, 32) = 256 blocks
    gemm_kernel<<<ggrid, 256>>>(x, w1, w2);
    stats_kernel<<<32, 512>>>(g1, b1, g2, b2);
    edge_kernel<<<2048, 128>>>(out);
}